// round 1
// baseline (speedup 1.0000x reference)
#include <cuda_runtime.h>
#include <math.h>

#define NUM_INITS 64
#define PSTRIDE   46922
#define NBATCH    128
#define TILE      16
#define NTILES    (NBATCH / TILE)     // 8
#define THREADS   384

// Param layout offsets (floats) within one init's row
#define OFF_WCONV 0        // [32][25]
#define OFF_BCONV 800      // [32]
#define OFF_WDENSE 832     // [10][4608]  (4608 = 32*144)
#define OFF_BDENSE 46912   // [10]

// Shared memory layout (in floats)
#define SM_IMG   0                       // 16 * 784 = 12544
#define SM_WC    (TILE * 784)            // 800 conv weights + 32 bias (contiguous)
#define SM_POOL  (SM_WC + 832)           // 16 * 148 (padded rows)
#define SM_WD    (SM_POOL + TILE * 148)  // 10 * 148 (padded rows)
#define SM_LOG   (SM_WD + 10 * 148)      // 16 * 10
#define SM_FLOATS (SM_LOG + 160)
#define SMEM_BYTES (SM_FLOATS * 4)       // 69536 B

__global__ void __launch_bounds__(THREADS, 2)
fused_paramevaler_kernel(const float* __restrict__ params,
                         const float* __restrict__ batch,
                         float* __restrict__ out)
{
    extern __shared__ float sm[];
    float* s_img  = sm + SM_IMG;
    float* s_wc   = sm + SM_WC;    // [c*25 + k], bias at s_wc[800+c]
    float* s_pool = sm + SM_POOL;  // [img*148 + r*12 + px]
    float* s_wd   = sm + SM_WD;    // [o*148 + j]
    float* s_log  = sm + SM_LOG;   // [img*10 + o]

    const int blk  = blockIdx.x;          // 0..511
    const int init = blk >> 3;            // / NTILES
    const int tile = blk & (NTILES - 1);
    const int n0   = tile * TILE;
    const int t    = threadIdx.x;

    const float* __restrict__ P = params + (size_t)init * PSTRIDE;

    // ---- Stage images (coalesced float4) ----
    {
        const float4* __restrict__ src = (const float4*)(batch + (size_t)n0 * 784);
        float4* dst = (float4*)s_img;
        #pragma unroll 1
        for (int k = t; k < TILE * 784 / 4; k += THREADS) dst[k] = src[k];
    }
    // ---- Stage conv weights + bias (832 contiguous floats; scalar: base only 8B-aligned) ----
    for (int k = t; k < 832; k += THREADS) s_wc[k] = P[k];
    __syncthreads();

    // Conv role: t -> (img, pooled row, half)
    const int img  = t / 24;        // 0..15
    const int rh   = t % 24;
    const int prow = rh >> 1;       // pooled row 0..11
    const int half = rh & 1;        // 0..1
    const int x0   = half * 12;     // conv-column base (0 or 12)
    const float* __restrict__ ip = s_img + img * 784 + prow * 2 * 28 + x0;

    // Dense role: t < 160 -> (n, o)
    const bool dact = (t < 160);
    const int  dn   = t / 10;
    const int  dob  = t - dn * 10;
    float acc0 = 0.f, acc1 = 0.f, acc2 = 0.f, acc3 = 0.f;

    const float* __restrict__ wdsrc = P + OFF_WDENSE;

    for (int c = 0; c < 32; ++c) {
        // Prefetch dense-weight chunk for channel c: [10][144] floats.
        // Params row is only 8B aligned -> float2 loads.
        if (t < 360) {
            int o = t / 36, q = t - o * 36;            // q = float4 slot 0..35
            const float2* wsp = (const float2*)(wdsrc + (size_t)o * 4608 + c * 144 + q * 4);
            float2 a = wsp[0], b = wsp[1];
            float4 v = make_float4(a.x, a.y, b.x, b.y);
            *(float4*)(s_wd + o * 148 + q * 4) = v;
        }

        // ---- Conv: 2 conv rows x 12 cols, register blocked ----
        const float* __restrict__ w = s_wc + c * 25;
        float c0[12], c1[12];
        #pragma unroll
        for (int x = 0; x < 12; ++x) { c0[x] = 0.f; c1[x] = 0.f; }

        #pragma unroll
        for (int ir = 0; ir < 6; ++ir) {
            float r_[16];
            const float* rp = ip + ir * 28;   // 16B-aligned (all offsets %4 == 0)
            #pragma unroll
            for (int q = 0; q < 4; ++q) {
                float4 v = *(const float4*)(rp + q * 4);
                r_[q*4+0] = v.x; r_[q*4+1] = v.y; r_[q*4+2] = v.z; r_[q*4+3] = v.w;
            }
            if (ir < 5) {
                #pragma unroll
                for (int kc = 0; kc < 5; ++kc) {
                    float wv = w[ir * 5 + kc];
                    #pragma unroll
                    for (int x = 0; x < 12; ++x) c0[x] = fmaf(r_[x + kc], wv, c0[x]);
                }
            }
            if (ir > 0) {
                #pragma unroll
                for (int kc = 0; kc < 5; ++kc) {
                    float wv = w[(ir - 1) * 5 + kc];
                    #pragma unroll
                    for (int x = 0; x < 12; ++x) c1[x] = fmaf(r_[x + kc], wv, c1[x]);
                }
            }
        }

        // ---- Pool(2x2) then +bias then ReLU (commutes with max) ----
        {
            float bc = s_wc[800 + c];
            float* pp = s_pool + img * 148 + prow * 12 + half * 6;
            #pragma unroll
            for (int p2 = 0; p2 < 6; ++p2) {
                float m = fmaxf(fmaxf(c0[2*p2], c0[2*p2+1]),
                                fmaxf(c1[2*p2], c1[2*p2+1]));
                pp[p2] = fmaxf(m + bc, 0.f);
            }
        }
        __syncthreads();   // pool written + s_wd staged

        // ---- Dense partial: acc[n][o] += <pool[n][c*144..], wd[o][c*144..]> ----
        if (dact) {
            const float* __restrict__ pl = s_pool + dn * 148;
            const float* __restrict__ wr = s_wd + dob * 148;
            #pragma unroll
            for (int q = 0; q < 36; q += 4) {
                {
                    float4 a = *(const float4*)(pl + (q+0)*4);
                    float4 b = *(const float4*)(wr + (q+0)*4);
                    acc0 += a.x*b.x + a.y*b.y + a.z*b.z + a.w*b.w;
                }
                {
                    float4 a = *(const float4*)(pl + (q+1)*4);
                    float4 b = *(const float4*)(wr + (q+1)*4);
                    acc1 += a.x*b.x + a.y*b.y + a.z*b.z + a.w*b.w;
                }
                {
                    float4 a = *(const float4*)(pl + (q+2)*4);
                    float4 b = *(const float4*)(wr + (q+2)*4);
                    acc2 += a.x*b.x + a.y*b.y + a.z*b.z + a.w*b.w;
                }
                {
                    float4 a = *(const float4*)(pl + (q+3)*4);
                    float4 b = *(const float4*)(wr + (q+3)*4);
                    acc3 += a.x*b.x + a.y*b.y + a.z*b.z + a.w*b.w;
                }
            }
        }
        __syncthreads();   // dense reads done; next channel may overwrite
    }

    // ---- Epilogue: bias, log_softmax over the 10 logits per image ----
    if (dact) {
        float logit = (acc0 + acc1) + (acc2 + acc3) + P[OFF_BDENSE + dob];
        s_log[dn * 10 + dob] = logit;
    }
    __syncthreads();

    if (t < TILE) {
        float v[10];
        float m = -1e30f;
        #pragma unroll
        for (int o = 0; o < 10; ++o) { v[o] = s_log[t * 10 + o]; m = fmaxf(m, v[o]); }
        float s = 0.f;
        #pragma unroll
        for (int o = 0; o < 10; ++o) s += expf(v[o] - m);
        float ls = m + logf(s);
        float* op = out + ((size_t)init * NBATCH + n0 + t) * 10;
        #pragma unroll
        for (int o = 0; o < 10; ++o) op[o] = v[o] - ls;
    }
}

extern "C" void kernel_launch(void* const* d_in, const int* in_sizes, int n_in,
                              void* d_out, int out_size)
{
    const float* params = (const float*)d_in[0];   // [64, 46922]
    const float* batch  = (const float*)d_in[1];   // [128, 1, 28, 28]
    float* out          = (float*)d_out;           // [64, 128, 10]

    cudaFuncSetAttribute(fused_paramevaler_kernel,
                         cudaFuncAttributeMaxDynamicSharedMemorySize, SMEM_BYTES);

    dim3 grid(NUM_INITS * NTILES);   // 512
    dim3 block(THREADS);             // 384
    fused_paramevaler_kernel<<<grid, block, SMEM_BYTES>>>(params, batch, out);
}